// round 4
// baseline (speedup 1.0000x reference)
#include <cuda_runtime.h>

#define T_STEPS 2048
#define BATCH   2048
#define HID     32

typedef unsigned long long u64;

#define S_SIG  (-1.4426950408889634f)   /* -log2(e)   */
#define S_TNH  (-2.8853900817779268f)   /* -2*log2(e) */

// ---- packed f32x2 helpers ----
__device__ __forceinline__ u64 ffma2(u64 a, u64 b, u64 c) {
    u64 d;
    asm("fma.rn.f32x2 %0, %1, %2, %3;" : "=l"(d) : "l"(a), "l"(b), "l"(c));
    return d;
}
__device__ __forceinline__ u64 pack2(float lo, float hi) {
    u64 d;
    asm("mov.b64 %0, {%1, %2};" : "=l"(d) : "f"(lo), "f"(hi));
    return d;
}
__device__ __forceinline__ void unpack2(u64 v, float& lo, float& hi) {
    asm("mov.b64 {%0, %1}, %2;" : "=f"(lo), "=f"(hi) : "l"(v));
}
// ---- fast activations; gate inputs arrive pre-scaled by S_SIG / S_TNH ----
__device__ __forceinline__ float ex2f(float x) {
    float y; asm("ex2.approx.f32 %0, %1;" : "=f"(y) : "f"(x)); return y;
}
__device__ __forceinline__ float rcpf(float x) {
    float y; asm("rcp.approx.f32 %0, %1;" : "=f"(y) : "f"(x)); return y;
}
__device__ __forceinline__ float gate_sig(float v)  { return rcpf(1.0f + ex2f(v)); }
__device__ __forceinline__ float gate_tanh(float v) { return fmaf(2.0f, rcpf(1.0f + ex2f(v)), -1.0f); }
__device__ __forceinline__ float tanh_c(float x)    { return fmaf(2.0f, rcpf(1.0f + ex2f(x * S_TNH)), -1.0f); }

// predicated STG.128, no BSSY/BSYNC
__device__ __forceinline__ void stg128_pred(int pred, float* p, float a, float b, float c, float d) {
    asm volatile("{\n\t"
                 ".reg .pred p;\n\t"
                 "setp.ne.u32 p, %0, 0;\n\t"
                 "@p st.global.v4.f32 [%1], {%2, %3, %4, %5};\n\t"
                 "}" :: "r"(pred), "l"(p), "f"(a), "f"(b), "f"(c), "f"(d) : "memory");
}

__global__ void __launch_bounds__(128, 1) lstm_kernel(
    const float* __restrict__ x,      // [T, B, 1]
    const float* __restrict__ W_ih,   // [4H, 1]
    const float* __restrict__ W_hh,   // [4H, H]
    const float* __restrict__ b_ih,   // [4H]
    const float* __restrict__ b_hh,   // [4H]
    const float* __restrict__ W_out,  // [1, H]
    const float* __restrict__ b_out,  // [1]
    float* __restrict__ out,          // [T*B] outs, then [B*H] hT, then [B*H] cT
    int out_size)
{
    const int lane = threadIdx.x & 31;
    const int wid  = threadIdx.x >> 5;
    const int w    = blockIdx.x * 4 + wid;   // 0..511
    const int b0   = 4 * w;                  // batches b0..b0+3

    // Per-lane weights, pre-scaled per gate (i,f,o: S_SIG; g: S_TNH).
    u64 w2[4][16];
    float wih[4], bias[4];
    #pragma unroll
    for (int g = 0; g < 4; g++) {
        const int row = g * 32 + lane;
        const float s = (g == 2) ? S_TNH : S_SIG;
        const float* wr = W_hh + row * HID;
        #pragma unroll
        for (int p = 0; p < 16; p++)
            w2[g][p] = pack2(wr[2 * p] * s, wr[2 * p + 1] * s);
        wih[g]  = W_ih[row] * s;
        bias[g] = (b_ih[row] + b_hh[row]) * s;
    }
    const float wout = W_out[lane];
    const float bout = b_out[0];

    // h broadcast staging: [warp][double-buffer][batch][hidden]
    __shared__ __align__(16) float sh[4][2][4][32];

    float h0 = 0.f, h1 = 0.f, h2 = 0.f, h3 = 0.f;
    float c0 = 0.f, c1 = 0.f, c2 = 0.f, c3 = 0.f;
    float rp0 = 0.f, rp1 = 0.f, rp2 = 0.f, rp3 = 0.f;  // deferred output partials

    const float* xp = x + b0;
    float4 xv = *reinterpret_cast<const float4*>(xp);
    float* outp = out + b0;
    const int store_pred = (lane == 0);

    #pragma unroll 1
    for (int t = 0; t < T_STEPS; t++) {
        const int buf = t & 1;
        // publish h(t-1)
        sh[wid][buf][0][lane] = h0;
        sh[wid][buf][1][lane] = h1;
        sh[wid][buf][2][lane] = h2;
        sh[wid][buf][3][lane] = h3;

        // clamped prefetch of next x
        const float* xpn = (t < T_STEPS - 1) ? (xp + BATCH) : xp;
        float4 xnext = *reinterpret_cast<const float4*>(xpn);
        xp = xpn;

        __syncwarp();

        // ---- deferred reduction of step t-1 output partials (hidden under matvec) ----
        float r0 = rp0, r1 = rp1, r2 = rp2, r3 = rp3;
        #pragma unroll
        for (int off = 16; off; off >>= 1) {
            r0 += __shfl_xor_sync(0xffffffffu, r0, off);
            r1 += __shfl_xor_sync(0xffffffffu, r1, off);
            r2 += __shfl_xor_sync(0xffffffffu, r2, off);
            r3 += __shfl_xor_sync(0xffffffffu, r3, off);
        }

        const double2* hp0 = reinterpret_cast<const double2*>(sh[wid][buf][0]);
        const double2* hp1 = reinterpret_cast<const double2*>(sh[wid][buf][1]);
        const double2* hp2 = reinterpret_cast<const double2*>(sh[wid][buf][2]);
        const double2* hp3 = reinterpret_cast<const double2*>(sh[wid][buf][3]);

        // ================= batches 0,1 =================
        u64 a0[4], a1[4];
        #pragma unroll
        for (int g = 0; g < 4; g++) {
            a0[g] = pack2(fmaf(xv.x, wih[g], bias[g]), 0.0f);
            a1[g] = pack2(fmaf(xv.y, wih[g], bias[g]), 0.0f);
        }
        #pragma unroll
        for (int q = 0; q < 8; q++) {
            double2 v0 = hp0[q], v1 = hp1[q];
            u64 p00 = __double_as_longlong(v0.x), p01 = __double_as_longlong(v0.y);
            u64 p10 = __double_as_longlong(v1.x), p11 = __double_as_longlong(v1.y);
            #pragma unroll
            for (int g = 0; g < 4; g++) {
                a0[g] = ffma2(p00, w2[g][2 * q], a0[g]);
                a1[g] = ffma2(p10, w2[g][2 * q], a1[g]);
            }
            #pragma unroll
            for (int g = 0; g < 4; g++) {
                a0[g] = ffma2(p01, w2[g][2 * q + 1], a0[g]);
                a1[g] = ffma2(p11, w2[g][2 * q + 1], a1[g]);
            }
        }
        // activations b0,b1 (MUFU chain hides under b2,b3 matvec below)
        {
            float lo, hi, vi, vf, vg, vo;
            unpack2(a0[0], lo, hi); vi = lo + hi;
            unpack2(a0[1], lo, hi); vf = lo + hi;
            unpack2(a0[2], lo, hi); vg = lo + hi;
            unpack2(a0[3], lo, hi); vo = lo + hi;
            float i = gate_sig(vi), f = gate_sig(vf), g = gate_tanh(vg), o = gate_sig(vo);
            c0 = fmaf(f, c0, i * g);
            h0 = o * tanh_c(c0);
            rp0 = h0 * wout;
        }
        {
            float lo, hi, vi, vf, vg, vo;
            unpack2(a1[0], lo, hi); vi = lo + hi;
            unpack2(a1[1], lo, hi); vf = lo + hi;
            unpack2(a1[2], lo, hi); vg = lo + hi;
            unpack2(a1[3], lo, hi); vo = lo + hi;
            float i = gate_sig(vi), f = gate_sig(vf), g = gate_tanh(vg), o = gate_sig(vo);
            c1 = fmaf(f, c1, i * g);
            h1 = o * tanh_c(c1);
            rp1 = h1 * wout;
        }

        // ================= batches 2,3 =================
        u64 a2[4], a3[4];
        #pragma unroll
        for (int g = 0; g < 4; g++) {
            a2[g] = pack2(fmaf(xv.z, wih[g], bias[g]), 0.0f);
            a3[g] = pack2(fmaf(xv.w, wih[g], bias[g]), 0.0f);
        }
        #pragma unroll
        for (int q = 0; q < 8; q++) {
            double2 v2 = hp2[q], v3 = hp3[q];
            u64 p20 = __double_as_longlong(v2.x), p21 = __double_as_longlong(v2.y);
            u64 p30 = __double_as_longlong(v3.x), p31 = __double_as_longlong(v3.y);
            #pragma unroll
            for (int g = 0; g < 4; g++) {
                a2[g] = ffma2(p20, w2[g][2 * q], a2[g]);
                a3[g] = ffma2(p30, w2[g][2 * q], a3[g]);
            }
            #pragma unroll
            for (int g = 0; g < 4; g++) {
                a2[g] = ffma2(p21, w2[g][2 * q + 1], a2[g]);
                a3[g] = ffma2(p31, w2[g][2 * q + 1], a3[g]);
            }
        }

        // store out[t-1]; at t==0 this writes a placeholder to out[0] that the
        // t==1 store overwrites (same thread, same address, in order).
        stg128_pred(store_pred, outp, r0 + bout, r1 + bout, r2 + bout, r3 + bout);
        outp += (t > 0) ? BATCH : 0;

        // activations b2,b3 (exposed tail)
        {
            float lo, hi, vi, vf, vg, vo;
            unpack2(a2[0], lo, hi); vi = lo + hi;
            unpack2(a2[1], lo, hi); vf = lo + hi;
            unpack2(a2[2], lo, hi); vg = lo + hi;
            unpack2(a2[3], lo, hi); vo = lo + hi;
            float i = gate_sig(vi), f = gate_sig(vf), g = gate_tanh(vg), o = gate_sig(vo);
            c2 = fmaf(f, c2, i * g);
            h2 = o * tanh_c(c2);
            rp2 = h2 * wout;
        }
        {
            float lo, hi, vi, vf, vg, vo;
            unpack2(a3[0], lo, hi); vi = lo + hi;
            unpack2(a3[1], lo, hi); vf = lo + hi;
            unpack2(a3[2], lo, hi); vg = lo + hi;
            unpack2(a3[3], lo, hi); vo = lo + hi;
            float i = gate_sig(vi), f = gate_sig(vf), g = gate_tanh(vg), o = gate_sig(vo);
            c3 = fmaf(f, c3, i * g);
            h3 = o * tanh_c(c3);
            rp3 = h3 * wout;
        }

        xv = xnext;
    }

    // epilogue: reduce final step partials -> out[T-1].
    // After the loop, outp already points at row T-1 (advanced 2047 times). NO extra advance.
    {
        float r0 = rp0, r1 = rp1, r2 = rp2, r3 = rp3;
        #pragma unroll
        for (int off = 16; off; off >>= 1) {
            r0 += __shfl_xor_sync(0xffffffffu, r0, off);
            r1 += __shfl_xor_sync(0xffffffffu, r1, off);
            r2 += __shfl_xor_sync(0xffffffffu, r2, off);
            r3 += __shfl_xor_sync(0xffffffffu, r3, off);
        }
        stg128_pred(store_pred, outp, r0 + bout, r1 + bout, r2 + bout, r3 + bout);
    }

    // final state (hT, cT), each [B, H], appended after outs
    if (out_size >= T_STEPS * BATCH + 2 * BATCH * HID) {
        float* hT = out + (size_t)T_STEPS * BATCH;
        float* cT = hT + BATCH * HID;
        hT[(size_t)(b0 + 0) * HID + lane] = h0;
        hT[(size_t)(b0 + 1) * HID + lane] = h1;
        hT[(size_t)(b0 + 2) * HID + lane] = h2;
        hT[(size_t)(b0 + 3) * HID + lane] = h3;
        cT[(size_t)(b0 + 0) * HID + lane] = c0;
        cT[(size_t)(b0 + 1) * HID + lane] = c1;
        cT[(size_t)(b0 + 2) * HID + lane] = c2;
        cT[(size_t)(b0 + 3) * HID + lane] = c3;
    }
}

extern "C" void kernel_launch(void* const* d_in, const int* in_sizes, int n_in,
                              void* d_out, int out_size) {
    const float* x     = (const float*)d_in[0];
    const float* W_ih  = (const float*)d_in[1];
    const float* W_hh  = (const float*)d_in[2];
    const float* b_ih  = (const float*)d_in[3];
    const float* b_hh  = (const float*)d_in[4];
    const float* W_out = (const float*)d_in[5];
    const float* b_out = (const float*)d_in[6];
    float* out = (float*)d_out;

    // 512 warps (4 batch elems each) = 128 CTAs of 128 threads, 1 CTA/SM
    lstm_kernel<<<128, 128>>>(x, W_ih, W_hh, b_ih, b_hh, W_out, b_out, out, out_size);
}

// round 5
// speedup vs baseline: 1.1738x; 1.1738x over previous
#include <cuda_runtime.h>

#define T_STEPS 2048
#define BATCH   2048
#define HID     32

typedef unsigned long long u64;

#define S_SIG  (-1.4426950408889634f)   /* -log2(e)   */
#define S_TNH  (-2.8853900817779268f)   /* -2*log2(e) */

// ---- packed f32x2 helpers ----
__device__ __forceinline__ u64 ffma2(u64 a, u64 b, u64 c) {
    u64 d;
    asm("fma.rn.f32x2 %0, %1, %2, %3;" : "=l"(d) : "l"(a), "l"(b), "l"(c));
    return d;
}
__device__ __forceinline__ u64 pack2(float lo, float hi) {
    u64 d;
    asm("mov.b64 %0, {%1, %2};" : "=l"(d) : "f"(lo), "f"(hi));
    return d;
}
__device__ __forceinline__ void unpack2(u64 v, float& lo, float& hi) {
    asm("mov.b64 {%0, %1}, %2;" : "=f"(lo), "=f"(hi) : "l"(v));
}
__device__ __forceinline__ float ex2f(float x) {
    float y; asm("ex2.approx.f32 %0, %1;" : "=f"(y) : "f"(x)); return y;
}
__device__ __forceinline__ float rcpf(float x) {
    float y; asm("rcp.approx.f32 %0, %1;" : "=f"(y) : "f"(x)); return y;
}

// predicated STG.64, no BSSY/BSYNC
__device__ __forceinline__ void stg64_pred(int pred, float* p, float a, float b) {
    asm volatile("{\n\t"
                 ".reg .pred p;\n\t"
                 "setp.ne.u32 p, %0, 0;\n\t"
                 "@p st.global.v2.f32 [%1], {%2, %3};\n\t"
                 "}" :: "r"(pred), "l"(p), "f"(a), "f"(b) : "memory");
}

__global__ void __launch_bounds__(128, 2) lstm_kernel(
    const float* __restrict__ x,      // [T, B, 1]
    const float* __restrict__ W_ih,   // [4H, 1]
    const float* __restrict__ W_hh,   // [4H, H]
    const float* __restrict__ b_ih,   // [4H]
    const float* __restrict__ b_hh,   // [4H]
    const float* __restrict__ W_out,  // [1, H]
    const float* __restrict__ b_out,  // [1]
    float* __restrict__ out,          // [T*B] outs, then [B*H] hT, then [B*H] cT
    int out_size)
{
    const int lane = threadIdx.x & 31;
    const int wid  = threadIdx.x >> 5;
    const int w    = blockIdx.x * 4 + wid;   // 0..1023
    const int b0   = 2 * w;                  // batch pair (b0, b0+1)

    // Per-lane weights, pre-scaled per gate (i,f,o: S_SIG; g: S_TNH).
    u64 w2[4][16];
    float wih[4], bias[4];
    #pragma unroll
    for (int g = 0; g < 4; g++) {
        const int row = g * 32 + lane;
        const float s = (g == 2) ? S_TNH : S_SIG;
        const float* wr = W_hh + row * HID;
        #pragma unroll
        for (int p = 0; p < 16; p++)
            w2[g][p] = pack2(wr[2 * p] * s, wr[2 * p + 1] * s);
        wih[g]  = W_ih[row] * s;
        bias[g] = (b_ih[row] + b_hh[row]) * s;
    }
    const float wout = W_out[lane];
    const float bout = b_out[0];

    // h broadcast staging: [warp][double-buffer][batch][hidden]
    __shared__ __align__(16) float sh[4][2][2][32];

    float h0 = 0.f, c0 = 0.f, h1 = 0.f, c1 = 0.f;
    float rp0 = 0.f, rp1 = 0.f;               // deferred output partials

    const float* xp = x + b0;
    float2 xv = *reinterpret_cast<const float2*>(xp);
    float* outp = out + b0;
    const int store_pred = (lane == 0);

    #pragma unroll 2
    for (int t = 0; t < T_STEPS; t++) {
        const int buf = t & 1;
        // publish h(t-1)
        sh[wid][buf][0][lane] = h0;
        sh[wid][buf][1][lane] = h1;

        // clamped prefetch of next x
        const float* xpn = (t < T_STEPS - 1) ? (xp + BATCH) : xp;
        float2 xnext = *reinterpret_cast<const float2*>(xpn);
        xp = xpn;

        // init gate accumulators: lo = x*wih + bias, hi = 0
        u64 acc0[4], acc1[4];
        #pragma unroll
        for (int g = 0; g < 4; g++) {
            acc0[g] = pack2(fmaf(xv.x, wih[g], bias[g]), 0.0f);
            acc1[g] = pack2(fmaf(xv.y, wih[g], bias[g]), 0.0f);
        }

        __syncwarp();

        // deferred reduction of step t-1 output partials (hidden under matvec)
        float r0 = rp0, r1 = rp1;
        #pragma unroll
        for (int off = 16; off; off >>= 1) {
            r0 += __shfl_xor_sync(0xffffffffu, r0, off);
            r1 += __shfl_xor_sync(0xffffffffu, r1, off);
        }

        // recurrent matvec: 8 chains (2 batches x 4 gates), 128 FFMA2
        const double2* hp0 = reinterpret_cast<const double2*>(sh[wid][buf][0]);
        const double2* hp1 = reinterpret_cast<const double2*>(sh[wid][buf][1]);
        #pragma unroll
        for (int q = 0; q < 8; q++) {
            double2 v0 = hp0[q], v1 = hp1[q];
            u64 p00 = __double_as_longlong(v0.x), p01 = __double_as_longlong(v0.y);
            u64 p10 = __double_as_longlong(v1.x), p11 = __double_as_longlong(v1.y);
            #pragma unroll
            for (int g = 0; g < 4; g++) {
                acc0[g] = ffma2(p00, w2[g][2 * q], acc0[g]);
                acc1[g] = ffma2(p10, w2[g][2 * q], acc1[g]);
            }
            #pragma unroll
            for (int g = 0; g < 4; g++) {
                acc0[g] = ffma2(p01, w2[g][2 * q + 1], acc0[g]);
                acc1[g] = ffma2(p11, w2[g][2 * q + 1], acc1[g]);
            }
        }

        // store out[t-1]; at t==0 writes a placeholder to out[0], overwritten at t==1
        stg64_pred(store_pred, outp, r0 + bout, r1 + bout);
        outp += (t > 0) ? BATCH : 0;

        // ---- horizontal adds ----
        float vi0, vf0, vg0, vo0, vi1, vf1, vg1, vo1;
        {
            float lo, hi;
            unpack2(acc0[0], lo, hi); vi0 = lo + hi;
            unpack2(acc0[1], lo, hi); vf0 = lo + hi;
            unpack2(acc0[2], lo, hi); vg0 = lo + hi;
            unpack2(acc0[3], lo, hi); vo0 = lo + hi;
            unpack2(acc1[0], lo, hi); vi1 = lo + hi;
            unpack2(acc1[1], lo, hi); vf1 = lo + hi;
            unpack2(acc1[2], lo, hi); vg1 = lo + hi;
            unpack2(acc1[3], lo, hi); vo1 = lo + hi;
        }

        // ---- quad-shared-rcp gates, batch 0 ----
        float i0g, f0g, o0g, g0g;
        {
            float Ei = ex2f(vi0), Ef = ex2f(vf0), Eg = ex2f(vg0), Eo = ex2f(vo0);
            float Pi = 1.f + Ei, Pf = 1.f + Ef, Pg = 1.f + Eg, Po = 1.f + Eo;
            float Pif = Pi * Pf, Pgo = Pg * Po;
            float R = rcpf(Pif * Pgo);
            float PgoR = Pgo * R;            // 1/Pif
            float PifR = Pif * R;            // 1/Pgo
            i0g = Pf * PgoR;                 // 1/Pi
            f0g = Pi * PgoR;                 // 1/Pf
            o0g = PifR * Pg;                 // 1/Po
            g0g = fmaf(2.f, PifR * Po, -1.f);// 2/Pg - 1
        }
        // ---- quad-shared-rcp gates, batch 1 ----
        float i1g, f1g, o1g, g1g;
        {
            float Ei = ex2f(vi1), Ef = ex2f(vf1), Eg = ex2f(vg1), Eo = ex2f(vo1);
            float Pi = 1.f + Ei, Pf = 1.f + Ef, Pg = 1.f + Eg, Po = 1.f + Eo;
            float Pif = Pi * Pf, Pgo = Pg * Po;
            float R = rcpf(Pif * Pgo);
            float PgoR = Pgo * R;
            float PifR = Pif * R;
            i1g = Pf * PgoR;
            f1g = Pi * PgoR;
            o1g = PifR * Pg;
            g1g = fmaf(2.f, PifR * Po, -1.f);
        }

        c0 = fmaf(f0g, c0, i0g * g0g);
        c1 = fmaf(f1g, c1, i1g * g1g);

        // ---- paired tanh(c): one rcp for both batches ----
        {
            // upper clamp: avoid inf*0 NaN when both E's overflow; at arg 63,
            // tanh is exactly +/-1 in fp32 anyway.
            float a0 = fminf(c0 * S_TNH, 63.f);
            float a1 = fminf(c1 * S_TNH, 63.f);
            float T0 = 1.f + ex2f(a0);
            float T1 = 1.f + ex2f(a1);
            float Rt = rcpf(T0 * T1);
            float th0 = fmaf(2.f, T1 * Rt, -1.f);   // 2/T0 - 1 = tanh(c0)
            float th1 = fmaf(2.f, T0 * Rt, -1.f);   // tanh(c1)
            h0 = o0g * th0;
            h1 = o1g * th1;
        }

        rp0 = h0 * wout;
        rp1 = h1 * wout;

        xv = xnext;
    }

    // epilogue: reduce final step partials -> out[T-1] (outp already at row T-1)
    {
        float r0 = rp0, r1 = rp1;
        #pragma unroll
        for (int off = 16; off; off >>= 1) {
            r0 += __shfl_xor_sync(0xffffffffu, r0, off);
            r1 += __shfl_xor_sync(0xffffffffu, r1, off);
        }
        stg64_pred(store_pred, outp, r0 + bout, r1 + bout);
    }

    // final state (hT, cT), each [B, H], appended after outs
    if (out_size >= T_STEPS * BATCH + 2 * BATCH * HID) {
        float* hT = out + (size_t)T_STEPS * BATCH;
        float* cT = hT + BATCH * HID;
        hT[(size_t)(b0 + 0) * HID + lane] = h0;
        hT[(size_t)(b0 + 1) * HID + lane] = h1;
        cT[(size_t)(b0 + 0) * HID + lane] = c0;
        cT[(size_t)(b0 + 1) * HID + lane] = c1;
    }
}

extern "C" void kernel_launch(void* const* d_in, const int* in_sizes, int n_in,
                              void* d_out, int out_size) {
    const float* x     = (const float*)d_in[0];
    const float* W_ih  = (const float*)d_in[1];
    const float* W_hh  = (const float*)d_in[2];
    const float* b_ih  = (const float*)d_in[3];
    const float* b_hh  = (const float*)d_in[4];
    const float* W_out = (const float*)d_in[5];
    const float* b_out = (const float*)d_in[6];
    float* out = (float*)d_out;

    // 1024 warps (2 batch elems each) = 256 CTAs of 128 threads, 2 CTA/SM
    lstm_kernel<<<256, 128>>>(x, W_ih, W_hh, b_ih, b_hh, W_out, b_out, out, out_size);
}